// round 1
// baseline (speedup 1.0000x reference)
#include <cuda_runtime.h>
#include <math.h>
#include <stdint.h>

#define NLEV 16
#define TBL (1u << 19)

struct LevelP {
    float scale[NLEV];
    uint32_t res[NLEV];
    uint32_t dense_mask;
};

__global__ __launch_bounds__(256, 2)
void ngp_fused_kernel(const float* __restrict__ gx,
                      const float* __restrict__ gd,
                      const float* __restrict__ table,
                      const float* __restrict__ w1,
                      const float* __restrict__ w2,
                      const float* __restrict__ wa1,
                      const float* __restrict__ wa2,
                      const float* __restrict__ wu1,
                      const float* __restrict__ wu2,
                      const float* __restrict__ wr1,
                      const float* __restrict__ wr2,
                      const float* __restrict__ wr3,
                      float* __restrict__ out,
                      int N, LevelP lp)
{
    // Transposed weights in SMEM: inner reduction dim contiguous -> float4 loads,
    // warp-uniform addresses (broadcast, conflict-free).
    __shared__ __align__(16) float s_w1T[64 * 32];   // w1T[j][i]  = w1[i][j]
    __shared__ __align__(16) float s_w2[64 * 16];    // row-major as-is
    __shared__ __align__(16) float s_wa1T[32 * 16];
    __shared__ __align__(16) float s_wa2[32];
    __shared__ __align__(16) float s_wu1T[32 * 16];
    __shared__ __align__(16) float s_wu2[32];
    __shared__ __align__(16) float s_wr1T[64 * 32];
    __shared__ __align__(16) float s_wr2T[64 * 64];
    __shared__ __align__(16) float s_wr3[64 * 3];

    for (int t = threadIdx.x; t < 64 * 32; t += blockDim.x) {
        int j = t >> 5, i = t & 31;
        s_w1T[t]  = w1[i * 64 + j];
        s_wr1T[t] = wr1[i * 64 + j];
    }
    for (int t = threadIdx.x; t < 64 * 64; t += blockDim.x) {
        int j = t >> 6, i = t & 63;
        s_wr2T[t] = wr2[i * 64 + j];
    }
    for (int t = threadIdx.x; t < 64 * 16; t += blockDim.x) s_w2[t] = w2[t];
    for (int t = threadIdx.x; t < 32 * 16; t += blockDim.x) {
        int j = t >> 4, i = t & 15;
        s_wa1T[t] = wa1[i * 32 + j];
        s_wu1T[t] = wu1[i * 32 + j];
    }
    for (int t = threadIdx.x; t < 64 * 3; t += blockDim.x) s_wr3[t] = wr3[t];
    if (threadIdx.x < 32) {
        s_wa2[threadIdx.x] = wa2[threadIdx.x];
        s_wu2[threadIdx.x] = wu2[threadIdx.x];
    }
    __syncthreads();

    int i0 = blockIdx.x * blockDim.x + threadIdx.x;
    if (i0 >= N) return;

    // x01 = (x + 1) * 0.5 -- exact rounding to match reference (no contraction)
    float px = __fmul_rn(__fadd_rn(gx[3 * i0 + 0], 1.0f), 0.5f);
    float py = __fmul_rn(__fadd_rn(gx[3 * i0 + 1], 1.0f), 0.5f);
    float pz = __fmul_rn(__fadd_rn(gx[3 * i0 + 2], 1.0f), 0.5f);

    // ---------------- grid encode: 16 levels x 8 corners x float2 ------------
    float enc[32];
    #pragma unroll
    for (int l = 0; l < NLEV; l++) {
        const float s = lp.scale[l];
        const uint32_t res = lp.res[l];
        const bool dense = (lp.dense_mask >> l) & 1u;

        // pos = x01 * s + 0.5 with two rounded ops (floor-sensitive path)
        float posx = __fadd_rn(__fmul_rn(px, s), 0.5f);
        float posy = __fadd_rn(__fmul_rn(py, s), 0.5f);
        float posz = __fadd_rn(__fmul_rn(pz, s), 0.5f);
        float gxf = floorf(posx), gyf = floorf(posy), gzf = floorf(posz);
        float fx = posx - gxf, fy = posy - gyf, fz = posz - gzf;
        uint32_t X = (uint32_t)gxf, Y = (uint32_t)gyf, Z = (uint32_t)gzf;

        const float2* tab = (const float2*)table + (size_t)l * TBL;

        uint32_t hy0 = Y * 2654435761u;
        uint32_t hy1 = (Y + 1u) * 2654435761u;
        uint32_t hz0 = Z * 805459861u;
        uint32_t hz1 = (Z + 1u) * 805459861u;
        uint32_t dy0 = Y * res,        dy1 = (Y + 1u) * res;
        uint32_t dz0 = Z * res * res,  dz1 = (Z + 1u) * res * res;

        float wx1 = fx, wx0 = 1.0f - fx;
        float wy1 = fy, wy0 = 1.0f - fy;
        float wz1 = fz, wz0 = 1.0f - fz;

        float e0 = 0.0f, e1 = 0.0f;
        #pragma unroll
        for (int c = 0; c < 8; c++) {
            const uint32_t bi = (c >> 2) & 1, bj = (c >> 1) & 1, bk = c & 1;
            uint32_t cx = X + bi;
            uint32_t idx;
            if (dense) {
                idx = cx + (bj ? dy1 : dy0) + (bk ? dz1 : dz0);
            } else {
                idx = (cx ^ (bj ? hy1 : hy0) ^ (bk ? hz1 : hz0)) & (TBL - 1u);
            }
            float w = (bi ? wx1 : wx0) * (bj ? wy1 : wy0) * (bk ? wz1 : wz0);
            float2 f = __ldg(tab + idx);
            e0 = fmaf(f.x, w, e0);
            e1 = fmaf(f.y, w, e1);
        }
        enc[2 * l + 0] = e0;
        enc[2 * l + 1] = e1;
    }

    // ---------------- h = relu(enc @ w1) @ w2   (streamed over hidden 64) ----
    float h[16];
    #pragma unroll
    for (int k = 0; k < 16; k++) h[k] = 0.0f;
    for (int j = 0; j < 64; j++) {
        const float4* wr = (const float4*)&s_w1T[j * 32];
        float acc = 0.0f;
        #pragma unroll
        for (int q = 0; q < 8; q++) {
            float4 w4 = wr[q];
            acc = fmaf(enc[4 * q + 0], w4.x, acc);
            acc = fmaf(enc[4 * q + 1], w4.y, acc);
            acc = fmaf(enc[4 * q + 2], w4.z, acc);
            acc = fmaf(enc[4 * q + 3], w4.w, acc);
        }
        float t1 = fmaxf(acc, 0.0f);
        const float4* w2r = (const float4*)&s_w2[j * 16];
        #pragma unroll
        for (int q = 0; q < 4; q++) {
            float4 w4 = w2r[q];
            h[4 * q + 0] = fmaf(t1, w4.x, h[4 * q + 0]);
            h[4 * q + 1] = fmaf(t1, w4.y, h[4 * q + 1]);
            h[4 * q + 2] = fmaf(t1, w4.z, h[4 * q + 2]);
            h[4 * q + 3] = fmaf(t1, w4.w, h[4 * q + 3]);
        }
    }

    // ---------------- sigma & uncert heads (streamed, scalar accumulators) ---
    float sacc = 0.0f, uacc = 0.0f;
    for (int j = 0; j < 32; j++) {
        const float4* wa = (const float4*)&s_wa1T[j * 16];
        const float4* wu = (const float4*)&s_wu1T[j * 16];
        float a = 0.0f, u = 0.0f;
        #pragma unroll
        for (int q = 0; q < 4; q++) {
            float4 a4 = wa[q];
            float4 u4 = wu[q];
            a = fmaf(h[4 * q + 0], a4.x, a);
            a = fmaf(h[4 * q + 1], a4.y, a);
            a = fmaf(h[4 * q + 2], a4.z, a);
            a = fmaf(h[4 * q + 3], a4.w, a);
            u = fmaf(h[4 * q + 0], u4.x, u);
            u = fmaf(h[4 * q + 1], u4.y, u);
            u = fmaf(h[4 * q + 2], u4.z, u);
            u = fmaf(h[4 * q + 3], u4.w, u);
        }
        sacc = fmaf(fmaxf(a, 0.0f), s_wa2[j], sacc);
        uacc = fmaf(u, s_wu2[j], uacc);
    }

    // ---------------- spherical harmonics (deg 4) ----------------------------
    // v = (d + 1) * 0.5 * 2 - 1, exact rounded-op chain (== (d+1) - 1 in fp32)
    float dxv = gd[3 * i0 + 0], dyv = gd[3 * i0 + 1], dzv = gd[3 * i0 + 2];
    float vx = __fadd_rn(__fadd_rn(dxv, 1.0f), -1.0f);
    float vy = __fadd_rn(__fadd_rn(dyv, 1.0f), -1.0f);
    float vz = __fadd_rn(__fadd_rn(dzv, 1.0f), -1.0f);

    float x2 = vx * vx, y2 = vy * vy, z2 = vz * vz;
    float xy = vx * vy, yz = vy * vz, xz = vx * vz;
    float sh[16];
    sh[0]  = 0.28209479177387814f;
    sh[1]  = -0.48860251190291987f * vy;
    sh[2]  = 0.48860251190291987f * vz;
    sh[3]  = -0.48860251190291987f * vx;
    sh[4]  = 1.0925484305920792f * xy;
    sh[5]  = -1.0925484305920792f * yz;
    sh[6]  = 0.94617469575756f * z2 - 0.31539156525252f;
    sh[7]  = -1.0925484305920792f * xz;
    sh[8]  = 0.5462742152960396f * (x2 - y2);
    sh[9]  = 0.5900435899266435f * vy * (-3.0f * x2 + y2);
    sh[10] = 2.890611442640554f * xy * vz;
    sh[11] = 0.4570457994644657f * vy * (1.0f - 5.0f * z2);
    sh[12] = 0.3731763325901154f * vz * (5.0f * z2 - 3.0f);
    sh[13] = 0.4570457994644657f * vx * (1.0f - 5.0f * z2);
    sh[14] = 1.445305721320277f * vz * (x2 - y2);
    sh[15] = 0.5900435899266435f * vx * (-x2 + 3.0f * y2);

    // ---------------- z1 = relu([sh, h] @ wr1) -------------------------------
    float z1[64];
    #pragma unroll
    for (int j = 0; j < 64; j++) {
        const float4* wr = (const float4*)&s_wr1T[j * 32];
        float acc = 0.0f;
        #pragma unroll
        for (int q = 0; q < 4; q++) {
            float4 w4 = wr[q];
            acc = fmaf(sh[4 * q + 0], w4.x, acc);
            acc = fmaf(sh[4 * q + 1], w4.y, acc);
            acc = fmaf(sh[4 * q + 2], w4.z, acc);
            acc = fmaf(sh[4 * q + 3], w4.w, acc);
        }
        #pragma unroll
        for (int q = 0; q < 4; q++) {
            float4 w4 = wr[4 + q];
            acc = fmaf(h[4 * q + 0], w4.x, acc);
            acc = fmaf(h[4 * q + 1], w4.y, acc);
            acc = fmaf(h[4 * q + 2], w4.z, acc);
            acc = fmaf(h[4 * q + 3], w4.w, acc);
        }
        z1[j] = fmaxf(acc, 0.0f);
    }

    // ---------------- rgb = sigmoid(relu(z1 @ wr2) @ wr3), streamed ----------
    float r0 = 0.0f, r1 = 0.0f, r2 = 0.0f;
    for (int j = 0; j < 64; j++) {
        const float4* wr = (const float4*)&s_wr2T[j * 64];
        float acc = 0.0f;
        #pragma unroll
        for (int q = 0; q < 16; q++) {
            float4 w4 = wr[q];
            acc = fmaf(z1[4 * q + 0], w4.x, acc);
            acc = fmaf(z1[4 * q + 1], w4.y, acc);
            acc = fmaf(z1[4 * q + 2], w4.z, acc);
            acc = fmaf(z1[4 * q + 3], w4.w, acc);
        }
        float z = fmaxf(acc, 0.0f);
        r0 = fmaf(z, s_wr3[j * 3 + 0], r0);
        r1 = fmaf(z, s_wr3[j * 3 + 1], r1);
        r2 = fmaf(z, s_wr3[j * 3 + 2], r2);
    }

    // ---------------- outputs: [sigmas(N) | rgbs(N,3) | uncerts(N)] ----------
    out[i0] = expf(sacc);
    out[N + 3 * i0 + 0] = 1.0f / (1.0f + expf(-r0));
    out[N + 3 * i0 + 1] = 1.0f / (1.0f + expf(-r1));
    out[N + 3 * i0 + 2] = 1.0f / (1.0f + expf(-r2));
    out[4 * N + i0] = expf(uacc);
}

extern "C" void kernel_launch(void* const* d_in, const int* in_sizes, int n_in,
                              void* d_out, int out_size) {
    const float* x     = (const float*)d_in[0];
    const float* d     = (const float*)d_in[1];
    const float* table = (const float*)d_in[2];
    const float* w1    = (const float*)d_in[3];
    const float* w2    = (const float*)d_in[4];
    const float* wa1   = (const float*)d_in[5];
    const float* wa2   = (const float*)d_in[6];
    const float* wu1   = (const float*)d_in[7];
    const float* wu2   = (const float*)d_in[8];
    const float* wr1   = (const float*)d_in[9];
    const float* wr2   = (const float*)d_in[10];
    const float* wr3   = (const float*)d_in[11];
    float* out = (float*)d_out;

    int N = in_sizes[0] / 3;

    LevelP lp;
    double Bv = exp(log(2048.0 / 16.0) / 15.0);
    uint32_t mask = 0;
    for (int l = 0; l < NLEV; l++) {
        double s = 16.0 * pow(Bv, (double)l) - 1.0;
        lp.scale[l] = (float)s;
        long long r = (long long)ceil(s) + 1;
        lp.res[l] = (uint32_t)r;
        if (r * r * r <= (long long)TBL) mask |= (1u << l);
    }
    lp.dense_mask = mask;

    int blocks = (N + 255) / 256;
    ngp_fused_kernel<<<blocks, 256>>>(x, d, table, w1, w2, wa1, wa2,
                                      wu1, wu2, wr1, wr2, wr3, out, N, lp);
}